// round 7
// baseline (speedup 1.0000x reference)
#include <cuda_runtime.h>
#include <cuda_bf16.h>
#include <math.h>
#include <stdint.h>

// ---------------- problem constants ----------------------------------------
#define BB   2
#define SS   1024
#define DD   1024
#define HH   16
#define DKK  64
#define FF   4096
#define LL   4
#define VV   32000
#define MM   (BB*SS)
#define LNEPS 1e-5f

// ---------------- device scratch (no allocation allowed) -------------------
__device__ float g_x  [MM*DD];
__device__ float g_qkv[MM*3*DD];
__device__ float g_ao [MM*DD];
__device__ float g_y  [MM*DD];
__device__ float g_ff [MM*FF];
__device__ float g_sc [(size_t)BB*HH*SS*SS];

// ---------------- helpers ---------------------------------------------------
__device__ __forceinline__ uint32_t smem_u32(const void* p) {
    uint32_t a;
    asm("{ .reg .u64 t; cvta.to.shared.u64 t, %1; cvt.u32.u64 %0, t; }"
        : "=r"(a) : "l"(p));
    return a;
}
#define LDSM_X4(r0, r1, r2, r3, addr) \
    asm volatile("ldmatrix.sync.aligned.m8n8.x4.shared.b16 {%0,%1,%2,%3}, [%4];" \
                 : "=r"(r0), "=r"(r1), "=r"(r2), "=r"(r3) : "r"(addr))
#define LDSM_X2(r0, r1, addr) \
    asm volatile("ldmatrix.sync.aligned.m8n8.x2.shared.b16 {%0,%1}, [%2];" \
                 : "=r"(r0), "=r"(r1) : "r"(addr))
#define MMA_BF16(c0, c1, c2, c3, a0, a1, a2, a3, b0, b1) \
    asm volatile("mma.sync.aligned.m16n8k16.row.col.f32.bf16.bf16.f32 " \
                 "{%0,%1,%2,%3}, {%4,%5,%6,%7}, {%8,%9}, {%0,%1,%2,%3};" \
                 : "+f"(c0), "+f"(c1), "+f"(c2), "+f"(c3) \
                 : "r"(a0), "r"(a1), "r"(a2), "r"(a3), "r"(b0), "r"(b1))

// split float4 -> packed hi-bf16x4 and lo-bf16x4
__device__ __forceinline__ void split4(float4 v, uint2& hi, uint2& lo) {
    uint32_t h0 = (uint32_t)__bfloat16_as_ushort(__float2bfloat16(v.x));
    uint32_t h1 = (uint32_t)__bfloat16_as_ushort(__float2bfloat16(v.y));
    uint32_t h2 = (uint32_t)__bfloat16_as_ushort(__float2bfloat16(v.z));
    uint32_t h3 = (uint32_t)__bfloat16_as_ushort(__float2bfloat16(v.w));
    hi.x = h0 | (h1 << 16);
    hi.y = h2 | (h3 << 16);
    float l0 = v.x - __uint_as_float(h0 << 16);
    float l1 = v.y - __uint_as_float(h1 << 16);
    float l2 = v.z - __uint_as_float(h2 << 16);
    float l3 = v.w - __uint_as_float(h3 << 16);
    uint32_t q0 = (uint32_t)__bfloat16_as_ushort(__float2bfloat16(l0));
    uint32_t q1 = (uint32_t)__bfloat16_as_ushort(__float2bfloat16(l1));
    uint32_t q2 = (uint32_t)__bfloat16_as_ushort(__float2bfloat16(l2));
    uint32_t q3 = (uint32_t)__bfloat16_as_ushort(__float2bfloat16(l3));
    lo.x = q0 | (q1 << 16);
    lo.y = q2 | (q3 << 16);
}

// ---------------- HMMA GEMM on fp32 operands: C = A[M,K] @ B[N,K]^T ---------
// CTA 64x128, 8 warps of 32x32, BK=32, double buffered, split-on-load,
// 3 MMA groups per chunk (hihi, hilo, lohi). 2 CTAs/SM target.
// Optional fused-N: B given as up-to-3 row-segment pointers of 1024 rows each
// (for QKV); bias segmented the same way.
#define SAST 40
#define A_ELEMS (64 * SAST)
#define B_ELEMS (128 * SAST)
#define GSMEM_BYTES ((2 * (A_ELEMS + B_ELEMS) * 2) * 2)   // 61440 B

__global__ __launch_bounds__(256, 2)
void gemm_f32(const float* __restrict__ A,
              const float* __restrict__ B0, const float* __restrict__ B1,
              const float* __restrict__ B2,
              const float* __restrict__ bias0, const float* __restrict__ bias1,
              const float* __restrict__ bias2,
              float* __restrict__ C, int M, int N, int K, int relu)
{
    extern __shared__ __nv_bfloat16 smem[];
    __nv_bfloat16* b1base = smem + 2 * A_ELEMS + 2 * B_ELEMS;
    __nv_bfloat16* tAhi[2] = { smem,                         b1base };
    __nv_bfloat16* tAlo[2] = { smem + A_ELEMS,               b1base + A_ELEMS };
    __nv_bfloat16* tBhi[2] = { smem + 2 * A_ELEMS,           b1base + 2 * A_ELEMS };
    __nv_bfloat16* tBlo[2] = { smem + 2 * A_ELEMS + B_ELEMS, b1base + 2 * A_ELEMS + B_ELEMS };

    int tid  = threadIdx.x;
    int lane = tid & 31;
    int wid  = tid >> 5;
    int wm   = (wid & 1) * 32;
    int wn   = (wid >> 1) * 32;
    int m0   = blockIdx.x * 64;     // M fast-varying: wave shares B tiles in L2
    int n0   = blockIdx.y * 128;

    float c[2][4][4];
#pragma unroll
    for (int i = 0; i < 2; i++)
#pragma unroll
        for (int j = 0; j < 4; j++)
#pragma unroll
            for (int r = 0; r < 4; r++) c[i][j][r] = 0.f;

    const int T = K >> 5;

    // loader geometry
    int arow = (tid + 0) >> 3,      acol = (tid & 7) * 4;          // A slot 0
    int arow1 = (tid + 256) >> 3,   acol1 = ((tid + 256) & 7) * 4; // A slot 1
    // B: 4 slots per thread
    int brow[4], bcol[4];
    const float* Bp[4];
#pragma unroll
    for (int j = 0; j < 4; j++) {
        int u = tid + j * 256;
        int r = u >> 3;
        bcol[j] = (u & 7) * 4;
        int gr = n0 + r;
        const float* p = B0;
        if (B1) {                              // fused QKV: 1024-row segments
            p = (gr < 1024) ? B0 : ((gr < 2048) ? B1 : B2);
            gr &= 1023;
        }
        brow[j] = r;
        Bp[j] = p + (size_t)gr * K;
    }
    const float* Ap0 = A + (size_t)(m0 + arow)  * K;
    const float* Ap1 = A + (size_t)(m0 + arow1) * K;

    float4 va[2], vb[4];
    va[0] = *(const float4*)(Ap0 + acol);
    va[1] = *(const float4*)(Ap1 + acol1);
#pragma unroll
    for (int j = 0; j < 4; j++) vb[j] = *(const float4*)(Bp[j] + bcol[j]);

    {
        uint2 h, l;
        split4(va[0], h, l);
        *(uint2*)(tAhi[0] + arow * SAST + acol) = h;
        *(uint2*)(tAlo[0] + arow * SAST + acol) = l;
        split4(va[1], h, l);
        *(uint2*)(tAhi[0] + arow1 * SAST + acol1) = h;
        *(uint2*)(tAlo[0] + arow1 * SAST + acol1) = l;
#pragma unroll
        for (int j = 0; j < 4; j++) {
            split4(vb[j], h, l);
            *(uint2*)(tBhi[0] + brow[j] * SAST + bcol[j]) = h;
            *(uint2*)(tBlo[0] + brow[j] * SAST + bcol[j]) = l;
        }
    }
    __syncthreads();

    for (int cc = 0; cc < T; ++cc) {
        int p = cc & 1;

        if (cc + 1 < T) {
            int k0 = (cc + 1) << 5;
            va[0] = *(const float4*)(Ap0 + k0 + acol);
            va[1] = *(const float4*)(Ap1 + k0 + acol1);
#pragma unroll
            for (int j = 0; j < 4; j++)
                vb[j] = *(const float4*)(Bp[j] + k0 + bcol[j]);
        }

        uint32_t bAhi = smem_u32(tAhi[p]);
        uint32_t bAlo = smem_u32(tAlo[p]);
        uint32_t bBhi = smem_u32(tBhi[p]);
        uint32_t bBlo = smem_u32(tBlo[p]);
#pragma unroll
        for (int kk = 0; kk < 32; kk += 16) {
            uint32_t ah[2][4], bh[4][2], t0, t1;
            uint32_t aoff = ((wm + (lane & 15)) * SAST + kk + ((lane >> 4) * 8)) * 2;
            uint32_t boff = ((wn + (lane & 7)) * SAST + kk + (((lane >> 3) & 1) * 8)) * 2;
#pragma unroll
            for (int ma = 0; ma < 2; ma++)
                LDSM_X4(ah[ma][0], ah[ma][1], ah[ma][2], ah[ma][3],
                        bAhi + aoff + ma * (16 * SAST * 2));
#pragma unroll
            for (int nb = 0; nb < 4; nb++)
                LDSM_X2(bh[nb][0], bh[nb][1], bBhi + boff + nb * (8 * SAST * 2));
            // group 1: hi * hi
#pragma unroll
            for (int ma = 0; ma < 2; ma++)
#pragma unroll
                for (int nb = 0; nb < 4; nb++)
                    MMA_BF16(c[ma][nb][0], c[ma][nb][1], c[ma][nb][2], c[ma][nb][3],
                             ah[ma][0], ah[ma][1], ah[ma][2], ah[ma][3],
                             bh[nb][0], bh[nb][1]);
            // group 2: hi * lo
#pragma unroll
            for (int nb = 0; nb < 4; nb++) {
                LDSM_X2(t0, t1, bBlo + boff + nb * (8 * SAST * 2));
#pragma unroll
                for (int ma = 0; ma < 2; ma++)
                    MMA_BF16(c[ma][nb][0], c[ma][nb][1], c[ma][nb][2], c[ma][nb][3],
                             ah[ma][0], ah[ma][1], ah[ma][2], ah[ma][3],
                             t0, t1);
            }
            // group 3: lo * hi
#pragma unroll
            for (int ma = 0; ma < 2; ma++) {
                uint32_t al0, al1, al2, al3;
                LDSM_X4(al0, al1, al2, al3, bAlo + aoff + ma * (16 * SAST * 2));
#pragma unroll
                for (int nb = 0; nb < 4; nb++)
                    MMA_BF16(c[ma][nb][0], c[ma][nb][1], c[ma][nb][2], c[ma][nb][3],
                             al0, al1, al2, al3, bh[nb][0], bh[nb][1]);
            }
        }

        if (cc + 1 < T) {
            int q = p ^ 1;
            uint2 h, l;
            split4(va[0], h, l);
            *(uint2*)(tAhi[q] + arow * SAST + acol) = h;
            *(uint2*)(tAlo[q] + arow * SAST + acol) = l;
            split4(va[1], h, l);
            *(uint2*)(tAhi[q] + arow1 * SAST + acol1) = h;
            *(uint2*)(tAlo[q] + arow1 * SAST + acol1) = l;
#pragma unroll
            for (int j = 0; j < 4; j++) {
                split4(vb[j], h, l);
                *(uint2*)(tBhi[q] + brow[j] * SAST + bcol[j]) = h;
                *(uint2*)(tBlo[q] + brow[j] * SAST + bcol[j]) = l;
            }
        }
        __syncthreads();
    }

    // ---- epilogue
#pragma unroll
    for (int ma = 0; ma < 2; ma++) {
        int mrow = m0 + wm + ma * 16 + (lane >> 2);
#pragma unroll
        for (int nb = 0; nb < 4; nb++) {
            int ncol = n0 + wn + nb * 8 + (lane & 3) * 2;
            float b0 = 0.f, b1 = 0.f;
            if (bias0) {
                const float* bb = bias0;
                int off = 0;
                if (bias1 && ncol >= 1024) {
                    if (ncol < 2048) { bb = bias1; off = 1024; }
                    else             { bb = bias2; off = 2048; }
                }
                b0 = bb[ncol - off]; b1 = bb[ncol + 1 - off];
            }
            float v00 = c[ma][nb][0] + b0, v01 = c[ma][nb][1] + b1;
            float v10 = c[ma][nb][2] + b0, v11 = c[ma][nb][3] + b1;
            if (relu) {
                v00 = fmaxf(v00, 0.f); v01 = fmaxf(v01, 0.f);
                v10 = fmaxf(v10, 0.f); v11 = fmaxf(v11, 0.f);
            }
            *(float2*)(C + (size_t)mrow * N + ncol)       = make_float2(v00, v01);
            *(float2*)(C + (size_t)(mrow + 8) * N + ncol) = make_float2(v10, v11);
        }
    }
}

// ---------------- embedding + sinusoidal PE ---------------------------------
__global__ void embed_pe_kernel(const int* __restrict__ ids,
                                const float* __restrict__ emb,
                                float* __restrict__ x)
{
    int idx = blockIdx.x * 256 + threadIdx.x;
    int m = idx >> 10;
    int d = idx & 1023;
    int s = m & (SS - 1);
    int tok = ids[m];
    int twohalf = (d >> 1) << 1;
    float div = __expf(-(float)twohalf * (9.210340371976184f / (float)DD));
    float ang = (float)s * div;
    float pe  = (d & 1) ? cosf(ang) : sinf(ang);
    x[idx] = emb[(size_t)tok * DD + d] * 32.0f + pe;
}

// ---------------- attention scores (packed qkv, causal, skip masked) --------
__global__ __launch_bounds__(256)
void attn_scores(const float* __restrict__ qkv, float* __restrict__ sc)
{
    int bh = blockIdx.z;
    int b = bh >> 4, h = bh & 15;
    int i0 = blockIdx.y * 128, j0 = blockIdx.x * 128;
    if (j0 > i0) return;
    float* out = sc + (size_t)bh * SS * SS;
    int tid = threadIdx.x;

    const float* qb = qkv + (size_t)b * SS * (3 * DD) + h * DKK;
    const float* kb = qb + DD;
    __shared__ float Qs[8][128];
    __shared__ float Ks[8][128];
    int lrow = tid >> 1, lcol = (tid & 1) << 2;
    int ty = tid >> 4, tx = tid & 15;
    float acc[8][8];
#pragma unroll
    for (int i = 0; i < 8; i++)
#pragma unroll
        for (int j = 0; j < 8; j++) acc[i][j] = 0.f;
    for (int k0 = 0; k0 < DKK; k0 += 8) {
        float4 av = *(const float4*)(qb + (size_t)(i0 + lrow) * (3 * DD) + k0 + lcol);
        float4 bv = *(const float4*)(kb + (size_t)(j0 + lrow) * (3 * DD) + k0 + lcol);
        __syncthreads();
        Qs[lcol + 0][lrow] = av.x; Qs[lcol + 1][lrow] = av.y;
        Qs[lcol + 2][lrow] = av.z; Qs[lcol + 3][lrow] = av.w;
        Ks[lcol + 0][lrow] = bv.x; Ks[lcol + 1][lrow] = bv.y;
        Ks[lcol + 2][lrow] = bv.z; Ks[lcol + 3][lrow] = bv.w;
        __syncthreads();
#pragma unroll
        for (int kk = 0; kk < 8; kk++) {
            float a[8], bb_[8];
#pragma unroll
            for (int i = 0; i < 8; i++) a[i]   = Qs[kk][ty * 8 + i];
#pragma unroll
            for (int j = 0; j < 8; j++) bb_[j] = Ks[kk][tx * 8 + j];
#pragma unroll
            for (int i = 0; i < 8; i++)
#pragma unroll
                for (int j = 0; j < 8; j++) acc[i][j] += a[i] * bb_[j];
        }
    }
    const float scale = 0.125f;
#pragma unroll
    for (int i = 0; i < 8; i++) {
        int row = i0 + ty * 8 + i;
#pragma unroll
        for (int j = 0; j < 8; j++) {
            int col = j0 + tx * 8 + j;
            float v = acc[i][j] * scale;
            if (col > row) v = -1e9f;
            out[(size_t)row * SS + col] = v;
        }
    }
}

// ---------------- causal row softmax (valid prefix only) --------------------
__global__ __launch_bounds__(256)
void softmax_rows(float* __restrict__ sc)
{
    int blk = blockIdx.x;
    int i  = blk & (SS - 1);
    int bh = blk >> 10;
    float* p = sc + (size_t)bh * SS * SS + (size_t)i * SS;
    int u = (i >> 8) + 1;
    int t = threadIdx.x, lane = t & 31, w = t >> 5;
    __shared__ float red[8];

    float v[4];
    float m = -3.0e38f;
    for (int s = 0; s < u; s++) {
        int j = t + s * 256;
        float val = (j <= i) ? p[j] : -1e9f;
        v[s] = val;
        m = fmaxf(m, val);
    }
#pragma unroll
    for (int o = 16; o > 0; o >>= 1) m = fmaxf(m, __shfl_xor_sync(~0u, m, o));
    if (lane == 0) red[w] = m;
    __syncthreads();
    m = red[0];
#pragma unroll
    for (int q = 1; q < 8; q++) m = fmaxf(m, red[q]);
    __syncthreads();

    float sum = 0.f;
    for (int s = 0; s < u; s++) { v[s] = __expf(v[s] - m); sum += v[s]; }
#pragma unroll
    for (int o = 16; o > 0; o >>= 1) sum += __shfl_xor_sync(~0u, sum, o);
    if (lane == 0) red[w] = sum;
    __syncthreads();
    sum = red[0];
#pragma unroll
    for (int q = 1; q < 8; q++) sum += red[q];

    float inv = 1.f / sum;
    for (int s = 0; s < u; s++) p[t + s * 256] = v[s] * inv;
}

// ---------------- o = attn @ v (packed qkv) -----------------------------------
__global__ __launch_bounds__(256)
void attn_av(const float* __restrict__ sc, const float* __restrict__ qkv,
             float* __restrict__ o)
{
    int bh = blockIdx.y;
    int b = bh >> 4, h = bh & 15;
    int i0 = blockIdx.x * 64;
    const float* A  = sc  + (size_t)bh * SS * SS;
    const float* vb = qkv + (size_t)b * SS * (3 * DD) + 2 * DD + h * DKK;
    __shared__ float As[16][64];
    __shared__ float Vs[16][64];
    int t  = threadIdx.x;
    int ar = t >> 2,  ac = (t & 3) << 2;
    int vr = t >> 4,  vc = (t & 15) << 2;
    int ty = t >> 4,  tx = t & 15;
    float acc[4][4];
#pragma unroll
    for (int i = 0; i < 4; i++)
#pragma unroll
        for (int j = 0; j < 4; j++) acc[i][j] = 0.f;
    int kmax = i0 + 64;
    for (int k0 = 0; k0 < kmax; k0 += 16) {
        float4 av = *(const float4*)(A  + (size_t)(i0 + ar) * SS + k0 + ac);
        float4 vv = *(const float4*)(vb + (size_t)(k0 + vr) * (3 * DD) + vc);
        __syncthreads();
        As[ac + 0][ar] = av.x; As[ac + 1][ar] = av.y;
        As[ac + 2][ar] = av.z; As[ac + 3][ar] = av.w;
        *(float4*)&Vs[vr][vc] = vv;
        __syncthreads();
#pragma unroll
        for (int kk = 0; kk < 16; kk++) {
            float a[4], bv_[4];
#pragma unroll
            for (int i = 0; i < 4; i++) a[i]   = As[kk][ty * 4 + i];
#pragma unroll
            for (int j = 0; j < 4; j++) bv_[j] = Vs[kk][tx * 4 + j];
#pragma unroll
            for (int i = 0; i < 4; i++)
#pragma unroll
                for (int j = 0; j < 4; j++) acc[i][j] += a[i] * bv_[j];
        }
    }
#pragma unroll
    for (int i = 0; i < 4; i++)
#pragma unroll
        for (int j = 0; j < 4; j++)
            o[(size_t)(b * SS + i0 + ty * 4 + i) * DD + h * DKK + tx * 4 + j]
                = acc[i][j];
}

// ---------------- fused residual + LayerNorm --------------------------------
__global__ __launch_bounds__(256)
void add_ln(const float* __restrict__ x, const float* __restrict__ y,
            const float* __restrict__ g, const float* __restrict__ bta,
            float* __restrict__ out)
{
    __shared__ float red[256];
    int row = blockIdx.x;
    int t = threadIdx.x;
    const float* xr = x + (size_t)row * DD;
    float v[4];
    float s = 0.f;
#pragma unroll
    for (int u = 0; u < 4; u++) {
        int idx = t + u * 256;
        float vv = xr[idx];
        if (y) vv += y[(size_t)row * DD + idx];
        v[u] = vv;
        s += vv;
    }
    red[t] = s; __syncthreads();
    for (int w = 128; w > 0; w >>= 1) {
        if (t < w) red[t] += red[t + w];
        __syncthreads();
    }
    float mean = red[0] * (1.f / DD); __syncthreads();
    float s2 = 0.f;
#pragma unroll
    for (int u = 0; u < 4; u++) { float d = v[u] - mean; s2 += d * d; }
    red[t] = s2; __syncthreads();
    for (int w = 128; w > 0; w >>= 1) {
        if (t < w) red[t] += red[t + w];
        __syncthreads();
    }
    float rstd = rsqrtf(red[0] * (1.f / DD) + LNEPS);
    float* orow = out + (size_t)row * DD;
#pragma unroll
    for (int u = 0; u < 4; u++) {
        int idx = t + u * 256;
        orow[idx] = (v[u] - mean) * rstd * g[idx] + bta[idx];
    }
}

// ---------------- host orchestration ----------------------------------------
extern "C" void kernel_launch(void* const* d_in, const int* in_sizes, int n_in,
                              void* d_out, int out_size)
{
    (void)in_sizes; (void)n_in; (void)out_size;
    const int*   ids    = (const int*)  d_in[0];
    const float* embedw = (const float*)d_in[1];
    const float* Wq     = (const float*)d_in[2];
    const float* bq     = (const float*)d_in[3];
    const float* Wk     = (const float*)d_in[4];
    const float* bk     = (const float*)d_in[5];
    const float* Wv     = (const float*)d_in[6];
    const float* bv     = (const float*)d_in[7];
    const float* Wo     = (const float*)d_in[8];
    const float* bo     = (const float*)d_in[9];
    const float* ln1_g  = (const float*)d_in[10];
    const float* ln1_b  = (const float*)d_in[11];
    const float* W1     = (const float*)d_in[12];
    const float* b1     = (const float*)d_in[13];
    const float* W2     = (const float*)d_in[14];
    const float* b2     = (const float*)d_in[15];
    const float* ln2_g  = (const float*)d_in[16];
    const float* ln2_b  = (const float*)d_in[17];
    const float* lnf_g  = (const float*)d_in[18];
    const float* lnf_b  = (const float*)d_in[19];
    const float* head_w = (const float*)d_in[20];
    float* out = (float*)d_out;

    float *x, *qkv, *ao, *y, *ff, *sc;
    cudaGetSymbolAddress((void**)&x,   g_x);
    cudaGetSymbolAddress((void**)&qkv, g_qkv);
    cudaGetSymbolAddress((void**)&ao,  g_ao);
    cudaGetSymbolAddress((void**)&y,   g_y);
    cudaGetSymbolAddress((void**)&ff,  g_ff);
    cudaGetSymbolAddress((void**)&sc,  g_sc);

    cudaFuncSetAttribute(gemm_f32, cudaFuncAttributeMaxDynamicSharedMemorySize,
                         GSMEM_BYTES);

    auto gemm = [&](const float* A, const float* B, const float* bias,
                    float* C, int M, int N, int K, int relu) {
        gemm_f32<<<dim3(M / 64, N / 128), 256, GSMEM_BYTES>>>(
            A, B, nullptr, nullptr, bias, nullptr, nullptr, C, M, N, K, relu);
    };

    embed_pe_kernel<<<(MM * DD) / 256, 256>>>(ids, embedw, x);

    dim3 gSc(SS / 128, SS / 128, BB * HH);
    dim3 gAv(SS / 64, BB * HH);

    for (int l = 0; l < LL; l++) {
        const float* wq = Wq + (size_t)l * DD * DD;
        const float* wk = Wk + (size_t)l * DD * DD;
        const float* wv = Wv + (size_t)l * DD * DD;
        const float* wo = Wo + (size_t)l * DD * DD;
        const float* w1 = W1 + (size_t)l * FF * DD;
        const float* w2 = W2 + (size_t)l * DD * FF;

        // fused QKV -> packed qkv[m][3*DD]
        gemm_f32<<<dim3(MM / 64, (3 * DD) / 128), 256, GSMEM_BYTES>>>(
            x, wq, wk, wv, bq + l * DD, bk + l * DD, bv + l * DD,
            qkv, MM, 3 * DD, DD, 0);

        attn_scores <<<gSc, 256>>>(qkv, sc);
        softmax_rows<<<BB * HH * SS, 256>>>(sc);
        attn_av     <<<gAv, 256>>>(sc, qkv, ao);

        gemm(ao, wo, bo + l * DD, y, MM, DD, DD, 0);
        add_ln<<<MM, 256>>>(x, y, ln1_g + l * DD, ln1_b + l * DD, x);

        gemm(x, w1, b1 + l * FF, ff, MM, FF, DD, 1);
        gemm(ff, w2, b2 + l * DD, y, MM, DD, FF, 0);
        add_ln<<<MM, 256>>>(x, y, ln2_g + l * DD, ln2_b + l * DD, x);
    }

    add_ln<<<MM, 256>>>(x, (const float*)nullptr, lnf_g, lnf_b, x);
    gemm(x, head_w, (const float*)nullptr, out, MM, VV, DD, 0);
}